// round 5
// baseline (speedup 1.0000x reference)
#include <cuda_runtime.h>
#include <cuda_bf16.h>
#include <cstdint>

// ---------------------------------------------------------------------------
// Problem constants (fixed shapes: x,y = [4096,1024] fp32, scalar output)
// ---------------------------------------------------------------------------
#define BROWS 4096
#define DDIM  1024
#define EPSF  1e-6f

// int8 quantization: q = round(448 * comp), |comp| <= ~0.16 for unit rows so
// no clipping. acc_s32 = 448^2 * S (exact integer accumulation).
// exp(S/tau) = exp2(acc * log2(e) / (0.07 * 448^2))
#define QSCALE_I 448.0f
#define K2LOG_I (20.6099287984152302f / 200704.0f)

// GEMM tiling: s8 mma.sync.m16n8k32 (legacy path). R3 established the pipe is
// MAC-rate-bound; int8 is the one dtype that historically runs 2x on this
// path. Tile config reverted to R3's best (128x256, 512 CTAs, 1 CTA/SM).
#define BM 128
#define BN 256
#define BK 128                  // int8 elements (=bytes) per K chunk
#define KT (DDIM / BK)          // 8 chunks
#define STAGES 3
#define RS (BK + 16)            // smem row stride (pad -> conflict-free LDSM)
#define STAGE_BYTES ((BM + BN) * RS)              // 55296
#define SMEM_BYTES (STAGES * STAGE_BYTES)         // 165888

// ---------------------------------------------------------------------------
// Scratch (device globals: allocation-free rule)
// ---------------------------------------------------------------------------
__device__ uint8_t g_xq[(size_t)BROWS * DDIM];   // s8, row-major, K contiguous
__device__ uint8_t g_yq[(size_t)BROWS * DDIM];
__device__ float g_rowsum[BROWS];
__device__ float g_colsum[BROWS];
__device__ float g_diag[BROWS];

// ---------------------------------------------------------------------------
// PTX helpers (all <= sm_80 features; nothing 'a'-gated)
// ---------------------------------------------------------------------------
static __device__ __forceinline__ uint32_t smem_u32(const void* p) {
    uint32_t a;
    asm("{ .reg .u64 t; cvta.to.shared.u64 t, %1; cvt.u32.u64 %0, t; }"
        : "=r"(a) : "l"(p));
    return a;
}

static __device__ __forceinline__ float ex2f(float x) {
    float y;
    asm("ex2.approx.ftz.f32 %0, %1;" : "=f"(y) : "f"(x));
    return y;
}

static __device__ __forceinline__ void cp16(uint32_t dst, const void* src) {
    asm volatile("cp.async.cg.shared.global [%0], [%1], 16;"
                 :: "r"(dst), "l"(src) : "memory");
}
#define CP_COMMIT() asm volatile("cp.async.commit_group;" ::: "memory")
#define CP_WAIT(n)  asm volatile("cp.async.wait_group %0;" :: "n"(n) : "memory")

static __device__ __forceinline__ void ldmatrix_x4(
    uint32_t& r0, uint32_t& r1, uint32_t& r2, uint32_t& r3, uint32_t addr) {
    asm volatile("ldmatrix.sync.aligned.m8n8.x4.shared.b16 {%0,%1,%2,%3}, [%4];"
                 : "=r"(r0), "=r"(r1), "=r"(r2), "=r"(r3) : "r"(addr));
}

// int8 MMA: D(16x8,s32) += A(16x32,s8) * B(32x8,s8)  (fragments == fp8 k32 layout)
static __device__ __forceinline__ void mma16832i(
    int32_t* d, const uint32_t* a, const uint32_t* b) {
    asm volatile(
        "mma.sync.aligned.m16n8k32.row.col.s32.s8.s8.s32 "
        "{%0,%1,%2,%3}, {%4,%5,%6,%7}, {%8,%9}, {%0,%1,%2,%3};"
        : "+r"(d[0]), "+r"(d[1]), "+r"(d[2]), "+r"(d[3])
        : "r"(a[0]), "r"(a[1]), "r"(a[2]), "r"(a[3]), "r"(b[0]), "r"(b[1]));
}

static __device__ __forceinline__ int32_t q8(float v) {
    return __float2int_rn(fminf(fmaxf(v, -127.f), 127.f));
}
static __device__ __forceinline__ uint32_t pack_s8x4(float a, float b, float c, float d) {
    return (uint32_t)(q8(a) & 0xff) | ((uint32_t)(q8(b) & 0xff) << 8) |
           ((uint32_t)(q8(c) & 0xff) << 16) | ((uint32_t)(q8(d) & 0xff) << 24);
}

// ---------------------------------------------------------------------------
// Kernel 1: block-per-row normalize -> s8 (scale 448), fp32 diag, zeroing
//   (R2 shape: 256 threads, 1 float4 of x and y per thread, regs ~34)
// ---------------------------------------------------------------------------
__global__ void __launch_bounds__(256) norm_kernel(
    const float* __restrict__ x, const float* __restrict__ y) {
    const int i = blockIdx.x;
    const int tid = threadIdx.x;
    const float4 xv = reinterpret_cast<const float4*>(x)[(size_t)i * 256 + tid];
    const float4 yv = reinterpret_cast<const float4*>(y)[(size_t)i * 256 + tid];

    float ssx = xv.x * xv.x + xv.y * xv.y + xv.z * xv.z + xv.w * xv.w;
    float ssy = yv.x * yv.x + yv.y * yv.y + yv.z * yv.z + yv.w * yv.w;
    float sxy = xv.x * yv.x + xv.y * yv.y + xv.z * yv.z + xv.w * yv.w;
#pragma unroll
    for (int m = 16; m; m >>= 1) {
        ssx += __shfl_xor_sync(0xffffffffu, ssx, m);
        ssy += __shfl_xor_sync(0xffffffffu, ssy, m);
        sxy += __shfl_xor_sync(0xffffffffu, sxy, m);
    }
    __shared__ float s0[8], s1[8], s2[8], sc[2];
    const int wid = tid >> 5, lane = tid & 31;
    if (lane == 0) { s0[wid] = ssx; s1[wid] = ssy; s2[wid] = sxy; }
    __syncthreads();
    if (tid == 0) {
        float a = 0.f, b = 0.f, c = 0.f;
#pragma unroll
        for (int w = 0; w < 8; ++w) { a += s0[w]; b += s1[w]; c += s2[w]; }
        const float invx = 1.0f / fmaxf(sqrtf(a), EPSF);
        const float invy = 1.0f / fmaxf(sqrtf(b), EPSF);
        sc[0] = invx; sc[1] = invy;
        g_diag[i] = c * invx * invy;
        g_rowsum[i] = 0.f;
        g_colsum[i] = 0.f;
    }
    __syncthreads();
    const float qx = QSCALE_I * sc[0], qy = QSCALE_I * sc[1];
    reinterpret_cast<uint32_t*>(g_xq + (size_t)i * DDIM)[tid] =
        pack_s8x4(xv.x * qx, xv.y * qx, xv.z * qx, xv.w * qx);
    reinterpret_cast<uint32_t*>(g_yq + (size_t)i * DDIM)[tid] =
        pack_s8x4(yv.x * qy, yv.y * qy, yv.z * qy, yv.w * qy);
}

// ---------------------------------------------------------------------------
// Kernel 2: pipelined s8 mma.sync GEMM tile + fused exp / row+col sums
//   grid = (32, 16); 512 threads; warp grid 4(m) x 4(n); warp tile 32x64
// ---------------------------------------------------------------------------
static __device__ __forceinline__ void load_stage(
    uint32_t sbase, int p, const uint8_t* gA, const uint8_t* gB, int tid) {
    const int s = p % STAGES;
    const uint32_t aBase = sbase + (uint32_t)(s * STAGE_BYTES);
    const uint32_t bBase = aBase + (uint32_t)(BM * RS);
    // A: 128 rows x 8 chunks(16B) = 1024 chunks, 2 per thread
#pragma unroll
    for (int r = 0; r < 2; ++r) {
        const int idx = tid + r * 512;
        const int row = idx >> 3, c = idx & 7;
        cp16(aBase + (uint32_t)(row * RS + c * 16),
             gA + (size_t)(p * BK) + (size_t)row * DDIM + c * 16);
    }
    // B: 256 rows x 8 chunks = 2048 chunks, 4 per thread
#pragma unroll
    for (int r = 0; r < 4; ++r) {
        const int idx = tid + r * 512;
        const int row = idx >> 3, c = idx & 7;
        cp16(bBase + (uint32_t)(row * RS + c * 16),
             gB + (size_t)(p * BK) + (size_t)row * DDIM + c * 16);
    }
    CP_COMMIT();
}

__global__ void __launch_bounds__(512, 1) gemm_exp_kernel() {
    extern __shared__ uint8_t smem[];
    const uint32_t sbase = smem_u32(smem);
    const int tid = threadIdx.x;
    const int lane = tid & 31;
    const int wid = tid >> 5;
    const int warp_m = wid & 3;        // 0..3 -> 32-row slice
    const int warp_n = wid >> 2;       // 0..3 -> 64-col slice
    const int i_base = blockIdx.x * BM;
    const int j_base = blockIdx.y * BN;
    const uint8_t* gA = g_xq + (size_t)i_base * DDIM;
    const uint8_t* gB = g_yq + (size_t)j_base * DDIM;

    int32_t acc[2][8][4];
#pragma unroll
    for (int mi = 0; mi < 2; ++mi)
#pragma unroll
        for (int ni = 0; ni < 8; ++ni)
#pragma unroll
            for (int r = 0; r < 4; ++r) acc[mi][ni][r] = 0;

    load_stage(sbase, 0, gA, gB, tid);
    load_stage(sbase, 1, gA, gB, tid);

    // ldmatrix: 16 rows x 32B; lanes 0-15 pick rows, lanes 16-31 add 16B
    const uint32_t lrow = (uint32_t)(lane & 15);
    const uint32_t koff = (uint32_t)((lane >> 4) * 16);

    for (int kt = 0; kt < KT; ++kt) {
        CP_WAIT(STAGES - 2);
        __syncthreads();              // single sync per stage (multistage-safe)
        if (kt + STAGES - 1 < KT)
            load_stage(sbase, kt + STAGES - 1, gA, gB, tid);

        const int s = kt % STAGES;
        const uint32_t aTile = sbase + (uint32_t)(s * STAGE_BYTES);
        const uint32_t bTile = aTile + (uint32_t)(BM * RS);
        const uint32_t aAddr0 = aTile + (warp_m * 32 + lrow) * RS + koff;
        const uint32_t bAddr0 = bTile + (warp_n * 64 + lrow) * RS + koff;

#pragma unroll
        for (int kk = 0; kk < 4; ++kk) {          // 4 x k32 = BK
            const uint32_t kb = (uint32_t)(kk * 32);
            uint32_t a[2][4];
#pragma unroll
            for (int mi = 0; mi < 2; ++mi)
                ldmatrix_x4(a[mi][0], a[mi][1], a[mi][2], a[mi][3],
                            aAddr0 + kb + (uint32_t)(mi * 16 * RS));
            uint32_t b[8][2];
#pragma unroll
            for (int p = 0; p < 4; ++p) {
                uint32_t r0, r1, r2, r3;
                ldmatrix_x4(r0, r1, r2, r3, bAddr0 + kb + (uint32_t)(p * 16 * RS));
                b[2 * p][0] = r0; b[2 * p + 1][0] = r1;
                b[2 * p][1] = r2; b[2 * p + 1][1] = r3;
            }
#pragma unroll
            for (int mi = 0; mi < 2; ++mi)
#pragma unroll
                for (int ni = 0; ni < 8; ++ni)
                    mma16832i(acc[mi][ni], a[mi], b[ni]);
        }
    }
    __syncthreads();   // protect final stage slot until all warps done (paranoia; free)

    // ---------------- fused epilogue: exp + row/col sums ----------------
    float rs[2][2] = {{0.f, 0.f}, {0.f, 0.f}};   // [mi][row-half]
    float cs[8][2];
#pragma unroll
    for (int ni = 0; ni < 8; ++ni) { cs[ni][0] = 0.f; cs[ni][1] = 0.f; }

#pragma unroll
    for (int mi = 0; mi < 2; ++mi)
#pragma unroll
        for (int ni = 0; ni < 8; ++ni) {
            const float e0 = ex2f(__int2float_rn(acc[mi][ni][0]) * K2LOG_I);
            const float e1 = ex2f(__int2float_rn(acc[mi][ni][1]) * K2LOG_I);
            const float e2 = ex2f(__int2float_rn(acc[mi][ni][2]) * K2LOG_I);
            const float e3 = ex2f(__int2float_rn(acc[mi][ni][3]) * K2LOG_I);
            rs[mi][0] += e0 + e1;      // row = m0 + mi*16 + gid
            rs[mi][1] += e2 + e3;      // row + 8
            cs[ni][0] += e0 + e2;      // col = n0 + ni*8 + 2*tig
            cs[ni][1] += e1 + e3;      // col + 1
        }

    const int m0 = i_base + warp_m * 32;
    const int n0 = j_base + warp_n * 64;
    const int gid = lane >> 2, tig = lane & 3;

#pragma unroll
    for (int mi = 0; mi < 2; ++mi)
#pragma unroll
        for (int h = 0; h < 2; ++h) {
            float v = rs[mi][h];
            v += __shfl_xor_sync(0xffffffffu, v, 1);
            v += __shfl_xor_sync(0xffffffffu, v, 2);
            if (tig == 0)
                atomicAdd(&g_rowsum[m0 + mi * 16 + h * 8 + gid], v);
        }
#pragma unroll
    for (int ni = 0; ni < 8; ++ni)
#pragma unroll
        for (int h = 0; h < 2; ++h) {
            float v = cs[ni][h];
            v += __shfl_xor_sync(0xffffffffu, v, 4);
            v += __shfl_xor_sync(0xffffffffu, v, 8);
            v += __shfl_xor_sync(0xffffffffu, v, 16);
            if (gid == 0)
                atomicAdd(&g_colsum[n0 + ni * 8 + 2 * tig + h], v);
        }
}

// ---------------------------------------------------------------------------
// Kernel 3: final log-reduce -> scalar loss
// ---------------------------------------------------------------------------
__global__ void __launch_bounds__(256) finalize_kernel(float* __restrict__ out) {
    const int tid = threadIdx.x;
    const double extra = (double)BROWS * 1e-6 + 1e-6;
    double acc = 0.0;
    for (int i = tid; i < BROWS; i += 256) {
        const double t = 2.0 * (double)g_diag[i] / 0.07;
        acc += t - log((double)g_rowsum[i] + extra) - log((double)g_colsum[i] + extra);
    }
    __shared__ double sb[256];
    sb[tid] = acc;
    __syncthreads();
#pragma unroll
    for (int s = 128; s; s >>= 1) {
        if (tid < s) sb[tid] += sb[tid + s];
        __syncthreads();
    }
    if (tid == 0) out[0] = (float)(sb[0] * (-1.0 / (2.0 * (double)BROWS)));
}

// ---------------------------------------------------------------------------
extern "C" void kernel_launch(void* const* d_in, const int* in_sizes, int n_in,
                              void* d_out, int out_size) {
    const float* x = (const float*)d_in[0];
    const float* y = (const float*)d_in[1];
    float* out = (float*)d_out;

    static int configured = 0;
    if (!configured) {
        cudaFuncSetAttribute(gemm_exp_kernel,
                             cudaFuncAttributeMaxDynamicSharedMemorySize, SMEM_BYTES);
        configured = 1;
    }

    norm_kernel<<<BROWS, 256>>>(x, y);
    gemm_exp_kernel<<<dim3(BROWS / BM, BROWS / BN), 512, SMEM_BYTES>>>();
    finalize_kernel<<<1, 256>>>(out);
}

// round 6
// speedup vs baseline: 1.7469x; 1.7469x over previous
#include <cuda_runtime.h>
#include <cuda_fp16.h>
#include <cuda_fp8.h>
#include <cstdint>

// ---------------------------------------------------------------------------
// Problem constants (fixed shapes: x,y = [4096,1024] fp32, scalar output)
// ---------------------------------------------------------------------------
#define BROWS 4096
#define DDIM  1024
#define EPSF  1e-6f

// fp8 quantization pre-scale (R3): e4m3 of 16*component; acc = 256*S.
// exp(S/tau) = exp2(acc * log2(e) / (0.07 * 256))
#define QSCALE 16.0f
#define K2LOG_S (20.6099287984152302f / 256.0f)

// GEMM tiling: fp8 e4m3 mma.sync.m16n8k32 with **f16 accumulator** (testing
// whether the legacy pipe doubles rate for f16-acc, Ada-style). R3 config:
// 128x256 tiles, 512 CTAs, 1 CTA/SM (measured best).
#define BM 128
#define BN 256
#define BK 128                  // fp8 elements (=bytes) per K chunk
#define KT (DDIM / BK)          // 8 chunks
#define STAGES 3
#define RS (BK + 16)            // smem row stride (pad -> conflict-free LDSM)
#define STAGE_BYTES ((BM + BN) * RS)              // 55296
#define SMEM_BYTES (STAGES * STAGE_BYTES)         // 165888

// ---------------------------------------------------------------------------
// Scratch (device globals: allocation-free rule)
// ---------------------------------------------------------------------------
__device__ uint8_t g_xq[(size_t)BROWS * DDIM];   // e4m3, row-major, K contiguous
__device__ uint8_t g_yq[(size_t)BROWS * DDIM];
__device__ float g_rowsum[BROWS];
__device__ float g_colsum[BROWS];
__device__ float g_diag[BROWS];

// ---------------------------------------------------------------------------
// PTX helpers (all <= sm_89 features; nothing 'a'-gated)
// ---------------------------------------------------------------------------
static __device__ __forceinline__ uint32_t smem_u32(const void* p) {
    uint32_t a;
    asm("{ .reg .u64 t; cvta.to.shared.u64 t, %1; cvt.u32.u64 %0, t; }"
        : "=r"(a) : "l"(p));
    return a;
}

static __device__ __forceinline__ float ex2f(float x) {
    float y;
    asm("ex2.approx.ftz.f32 %0, %1;" : "=f"(y) : "f"(x));
    return y;
}

static __device__ __forceinline__ void cp16(uint32_t dst, const void* src) {
    asm volatile("cp.async.cg.shared.global [%0], [%1], 16;"
                 :: "r"(dst), "l"(src) : "memory");
}
#define CP_COMMIT() asm volatile("cp.async.commit_group;" ::: "memory")
#define CP_WAIT(n)  asm volatile("cp.async.wait_group %0;" :: "n"(n) : "memory")

static __device__ __forceinline__ void ldmatrix_x4(
    uint32_t& r0, uint32_t& r1, uint32_t& r2, uint32_t& r3, uint32_t addr) {
    asm volatile("ldmatrix.sync.aligned.m8n8.x4.shared.b16 {%0,%1,%2,%3}, [%4];"
                 : "=r"(r0), "=r"(r1), "=r"(r2), "=r"(r3) : "r"(addr));
}

// fp8 e4m3 MMA, f16 accumulator: D(16x8,f16) += A(16x32,e4m3) * B(32x8,e4m3)
// d[0] = halves (r, c), (r, c+1); d[1] = halves (r+8, c), (r+8, c+1)
static __device__ __forceinline__ void mma16832_h(
    uint32_t* d, const uint32_t* a, const uint32_t* b) {
    asm volatile(
        "mma.sync.aligned.m16n8k32.row.col.f16.e4m3.e4m3.f16 "
        "{%0,%1}, {%2,%3,%4,%5}, {%6,%7}, {%0,%1};"
        : "+r"(d[0]), "+r"(d[1])
        : "r"(a[0]), "r"(a[1]), "r"(a[2]), "r"(a[3]), "r"(b[0]), "r"(b[1]));
}

static __device__ __forceinline__ uint32_t pack_fp8x4(
    float a, float b, float c, float d) {
    const __nv_fp8x2_storage_t lo =
        __nv_cvt_float2_to_fp8x2(make_float2(a, b), __NV_SATFINITE, __NV_E4M3);
    const __nv_fp8x2_storage_t hi =
        __nv_cvt_float2_to_fp8x2(make_float2(c, d), __NV_SATFINITE, __NV_E4M3);
    return (uint32_t)lo | ((uint32_t)hi << 16);
}

// ---------------------------------------------------------------------------
// Kernel 1: block-per-row normalize -> e4m3 (scale 16), fp32 diag, zeroing
// ---------------------------------------------------------------------------
__global__ void __launch_bounds__(256) norm_kernel(
    const float* __restrict__ x, const float* __restrict__ y) {
    const int i = blockIdx.x;
    const int tid = threadIdx.x;
    const float4 xv = reinterpret_cast<const float4*>(x)[(size_t)i * 256 + tid];
    const float4 yv = reinterpret_cast<const float4*>(y)[(size_t)i * 256 + tid];

    float ssx = xv.x * xv.x + xv.y * xv.y + xv.z * xv.z + xv.w * xv.w;
    float ssy = yv.x * yv.x + yv.y * yv.y + yv.z * yv.z + yv.w * yv.w;
    float sxy = xv.x * yv.x + xv.y * yv.y + xv.z * yv.z + xv.w * yv.w;
#pragma unroll
    for (int m = 16; m; m >>= 1) {
        ssx += __shfl_xor_sync(0xffffffffu, ssx, m);
        ssy += __shfl_xor_sync(0xffffffffu, ssy, m);
        sxy += __shfl_xor_sync(0xffffffffu, sxy, m);
    }
    __shared__ float s0[8], s1[8], s2[8], sc[2];
    const int wid = tid >> 5, lane = tid & 31;
    if (lane == 0) { s0[wid] = ssx; s1[wid] = ssy; s2[wid] = sxy; }
    __syncthreads();
    if (tid == 0) {
        float a = 0.f, b = 0.f, c = 0.f;
#pragma unroll
        for (int w = 0; w < 8; ++w) { a += s0[w]; b += s1[w]; c += s2[w]; }
        const float invx = 1.0f / fmaxf(sqrtf(a), EPSF);
        const float invy = 1.0f / fmaxf(sqrtf(b), EPSF);
        sc[0] = invx; sc[1] = invy;
        g_diag[i] = c * invx * invy;
        g_rowsum[i] = 0.f;
        g_colsum[i] = 0.f;
    }
    __syncthreads();
    const float qx = QSCALE * sc[0], qy = QSCALE * sc[1];
    reinterpret_cast<uint32_t*>(g_xq + (size_t)i * DDIM)[tid] =
        pack_fp8x4(xv.x * qx, xv.y * qx, xv.z * qx, xv.w * qx);
    reinterpret_cast<uint32_t*>(g_yq + (size_t)i * DDIM)[tid] =
        pack_fp8x4(yv.x * qy, yv.y * qy, yv.z * qy, yv.w * qy);
}

// ---------------------------------------------------------------------------
// Kernel 2: pipelined fp8 (f16-acc) GEMM tile + fused exp / row+col sums
//   grid = (32, 16); 512 threads; warp grid 4(m) x 4(n); warp tile 32x64
// ---------------------------------------------------------------------------
static __device__ __forceinline__ void load_stage(
    uint32_t sbase, int p, const uint8_t* gA, const uint8_t* gB, int tid) {
    const int s = p % STAGES;
    const uint32_t aBase = sbase + (uint32_t)(s * STAGE_BYTES);
    const uint32_t bBase = aBase + (uint32_t)(BM * RS);
    // A: 128 rows x 8 chunks(16B) = 1024 chunks, 2 per thread
#pragma unroll
    for (int r = 0; r < 2; ++r) {
        const int idx = tid + r * 512;
        const int row = idx >> 3, c = idx & 7;
        cp16(aBase + (uint32_t)(row * RS + c * 16),
             gA + (size_t)(p * BK) + (size_t)row * DDIM + c * 16);
    }
    // B: 256 rows x 8 chunks = 2048 chunks, 4 per thread
#pragma unroll
    for (int r = 0; r < 4; ++r) {
        const int idx = tid + r * 512;
        const int row = idx >> 3, c = idx & 7;
        cp16(bBase + (uint32_t)(row * RS + c * 16),
             gB + (size_t)(p * BK) + (size_t)row * DDIM + c * 16);
    }
    CP_COMMIT();
}

__global__ void __launch_bounds__(512, 1) gemm_exp_kernel() {
    extern __shared__ uint8_t smem[];
    const uint32_t sbase = smem_u32(smem);
    const int tid = threadIdx.x;
    const int lane = tid & 31;
    const int wid = tid >> 5;
    const int warp_m = wid & 3;        // 0..3 -> 32-row slice
    const int warp_n = wid >> 2;       // 0..3 -> 64-col slice
    const int i_base = blockIdx.x * BM;
    const int j_base = blockIdx.y * BN;
    const uint8_t* gA = g_xq + (size_t)i_base * DDIM;
    const uint8_t* gB = g_yq + (size_t)j_base * DDIM;

    uint32_t acc[2][8][2];             // f16x2 accumulators
#pragma unroll
    for (int mi = 0; mi < 2; ++mi)
#pragma unroll
        for (int ni = 0; ni < 8; ++ni) { acc[mi][ni][0] = 0u; acc[mi][ni][1] = 0u; }

    load_stage(sbase, 0, gA, gB, tid);
    load_stage(sbase, 1, gA, gB, tid);

    // ldmatrix: 16 rows x 32B; lanes 0-15 pick rows, lanes 16-31 add 16B
    const uint32_t lrow = (uint32_t)(lane & 15);
    const uint32_t koff = (uint32_t)((lane >> 4) * 16);

    for (int kt = 0; kt < KT; ++kt) {
        CP_WAIT(STAGES - 2);
        __syncthreads();              // single sync per stage (multistage-safe)
        if (kt + STAGES - 1 < KT)
            load_stage(sbase, kt + STAGES - 1, gA, gB, tid);

        const int s = kt % STAGES;
        const uint32_t aTile = sbase + (uint32_t)(s * STAGE_BYTES);
        const uint32_t bTile = aTile + (uint32_t)(BM * RS);
        const uint32_t aAddr0 = aTile + (warp_m * 32 + lrow) * RS + koff;
        const uint32_t bAddr0 = bTile + (warp_n * 64 + lrow) * RS + koff;

#pragma unroll
        for (int kk = 0; kk < 4; ++kk) {          // 4 x k32 = BK
            const uint32_t kb = (uint32_t)(kk * 32);
            uint32_t a[2][4];
#pragma unroll
            for (int mi = 0; mi < 2; ++mi)
                ldmatrix_x4(a[mi][0], a[mi][1], a[mi][2], a[mi][3],
                            aAddr0 + kb + (uint32_t)(mi * 16 * RS));
            uint32_t b[8][2];
#pragma unroll
            for (int p = 0; p < 4; ++p) {
                uint32_t r0, r1, r2, r3;
                ldmatrix_x4(r0, r1, r2, r3, bAddr0 + kb + (uint32_t)(p * 16 * RS));
                b[2 * p][0] = r0; b[2 * p + 1][0] = r1;
                b[2 * p][1] = r2; b[2 * p + 1][1] = r3;
            }
#pragma unroll
            for (int mi = 0; mi < 2; ++mi)
#pragma unroll
                for (int ni = 0; ni < 8; ++ni)
                    mma16832_h(acc[mi][ni], a[mi], b[ni]);
        }
    }
    __syncthreads();

    // ---------------- fused epilogue: exp + row/col sums ----------------
    float rs[2][2] = {{0.f, 0.f}, {0.f, 0.f}};   // [mi][row-half]
    float cs[8][2];
#pragma unroll
    for (int ni = 0; ni < 8; ++ni) { cs[ni][0] = 0.f; cs[ni][1] = 0.f; }

#pragma unroll
    for (int mi = 0; mi < 2; ++mi)
#pragma unroll
        for (int ni = 0; ni < 8; ++ni) {
            const float2 p0 = __half22float2(*reinterpret_cast<__half2*>(&acc[mi][ni][0]));
            const float2 p1 = __half22float2(*reinterpret_cast<__half2*>(&acc[mi][ni][1]));
            const float e0 = ex2f(p0.x * K2LOG_S);   // (row r,   col c)
            const float e1 = ex2f(p0.y * K2LOG_S);   // (row r,   col c+1)
            const float e2 = ex2f(p1.x * K2LOG_S);   // (row r+8, col c)
            const float e3 = ex2f(p1.y * K2LOG_S);   // (row r+8, col c+1)
            rs[mi][0] += e0 + e1;
            rs[mi][1] += e2 + e3;
            cs[ni][0] += e0 + e2;
            cs[ni][1] += e1 + e3;
        }

    const int m0 = i_base + warp_m * 32;
    const int n0 = j_base + warp_n * 64;
    const int gid = lane >> 2, tig = lane & 3;

#pragma unroll
    for (int mi = 0; mi < 2; ++mi)
#pragma unroll
        for (int h = 0; h < 2; ++h) {
            float v = rs[mi][h];
            v += __shfl_xor_sync(0xffffffffu, v, 1);
            v += __shfl_xor_sync(0xffffffffu, v, 2);
            if (tig == 0)
                atomicAdd(&g_rowsum[m0 + mi * 16 + h * 8 + gid], v);
        }
#pragma unroll
    for (int ni = 0; ni < 8; ++ni)
#pragma unroll
        for (int h = 0; h < 2; ++h) {
            float v = cs[ni][h];
            v += __shfl_xor_sync(0xffffffffu, v, 4);
            v += __shfl_xor_sync(0xffffffffu, v, 8);
            v += __shfl_xor_sync(0xffffffffu, v, 16);
            if (gid == 0)
                atomicAdd(&g_colsum[n0 + ni * 8 + 2 * tig + h], v);
        }
}

// ---------------------------------------------------------------------------
// Kernel 3: final log-reduce -> scalar loss
// ---------------------------------------------------------------------------
__global__ void __launch_bounds__(256) finalize_kernel(float* __restrict__ out) {
    const int tid = threadIdx.x;
    const double extra = (double)BROWS * 1e-6 + 1e-6;
    double acc = 0.0;
    for (int i = tid; i < BROWS; i += 256) {
        const double t = 2.0 * (double)g_diag[i] / 0.07;
        acc += t - log((double)g_rowsum[i] + extra) - log((double)g_colsum[i] + extra);
    }
    __shared__ double sb[256];
    sb[tid] = acc;
    __syncthreads();
#pragma unroll
    for (int s = 128; s; s >>= 1) {
        if (tid < s) sb[tid] += sb[tid + s];
        __syncthreads();
    }
    if (tid == 0) out[0] = (float)(sb[0] * (-1.0 / (2.0 * (double)BROWS)));
}

// ---------------------------------------------------------------------------
extern "C" void kernel_launch(void* const* d_in, const int* in_sizes, int n_in,
                              void* d_out, int out_size) {
    const float* x = (const float*)d_in[0];
    const float* y = (const float*)d_in[1];
    float* out = (float*)d_out;

    static int configured = 0;
    if (!configured) {
        cudaFuncSetAttribute(gemm_exp_kernel,
                             cudaFuncAttributeMaxDynamicSharedMemorySize, SMEM_BYTES);
        configured = 1;
    }

    norm_kernel<<<BROWS, 256>>>(x, y);
    gemm_exp_kernel<<<dim3(BROWS / BM, BROWS / BN), 512, SMEM_BYTES>>>();
    finalize_kernel<<<1, 256>>>(out);
}

// round 7
// speedup vs baseline: 1.8361x; 1.0511x over previous
#include <cuda_runtime.h>
#include <cuda_fp8.h>
#include <cstdint>

// ---------------------------------------------------------------------------
// Problem constants (fixed shapes: x,y = [4096,1024] fp32, scalar output)
// ---------------------------------------------------------------------------
#define BROWS 4096
#define DDIM  1024
#define EPSF  1e-6f

// fp8 quantization pre-scale (R3): e4m3 of 16*component; acc = 256*S.
// exp(S/tau) = exp2(acc * log2(e) / (0.07 * 256))
#define QSCALE 16.0f
#define K2LOG_S (20.6099287984152302f / 256.0f)

// GEMM tiling: fp8 e4m3 mma.sync.m16n8k32, f32 acc (R3 = best measured).
// R6 conclusion: legacy pipe is rate-invariant (~315 MAC/cyc/SM); remaining
// GEMM loss is wave quantization (512 CTAs = 3.46 waves -> 4-wave makespan).
// -> 128x128 tiles, 1024 CTAs (6.92 waves, ~1% tail), still 1 CTA/SM with
//    full register budget (R4's regression = 2-CTA reg cap, avoided here).
#define BM 128
#define BN 128
#define BK 128                  // fp8 elements (=bytes) per K chunk
#define KT (DDIM / BK)          // 8 chunks
#define STAGES 4
#define RS (BK + 16)            // smem row stride (pad -> conflict-free LDSM)
#define STAGE_BYTES ((BM + BN) * RS)              // 36864
#define SMEM_BYTES (STAGES * STAGE_BYTES)         // 147456

// ---------------------------------------------------------------------------
// Scratch (device globals: allocation-free rule)
// ---------------------------------------------------------------------------
__device__ uint8_t g_xq[(size_t)BROWS * DDIM];   // e4m3, row-major, K contiguous
__device__ uint8_t g_yq[(size_t)BROWS * DDIM];
__device__ float g_rowsum[BROWS];
__device__ float g_colsum[BROWS];
__device__ float g_diag[BROWS];

// ---------------------------------------------------------------------------
// PTX helpers (all <= sm_89 features; nothing 'a'-gated)
// ---------------------------------------------------------------------------
static __device__ __forceinline__ uint32_t smem_u32(const void* p) {
    uint32_t a;
    asm("{ .reg .u64 t; cvta.to.shared.u64 t, %1; cvt.u32.u64 %0, t; }"
        : "=r"(a) : "l"(p));
    return a;
}

static __device__ __forceinline__ float ex2f(float x) {
    float y;
    asm("ex2.approx.ftz.f32 %0, %1;" : "=f"(y) : "f"(x));
    return y;
}

static __device__ __forceinline__ void cp16(uint32_t dst, const void* src) {
    asm volatile("cp.async.cg.shared.global [%0], [%1], 16;"
                 :: "r"(dst), "l"(src) : "memory");
}
#define CP_COMMIT() asm volatile("cp.async.commit_group;" ::: "memory")
#define CP_WAIT(n)  asm volatile("cp.async.wait_group %0;" :: "n"(n) : "memory")

static __device__ __forceinline__ void ldmatrix_x4(
    uint32_t& r0, uint32_t& r1, uint32_t& r2, uint32_t& r3, uint32_t addr) {
    asm volatile("ldmatrix.sync.aligned.m8n8.x4.shared.b16 {%0,%1,%2,%3}, [%4];"
                 : "=r"(r0), "=r"(r1), "=r"(r2), "=r"(r3) : "r"(addr));
}

// fp8 e4m3 MMA: D(16x8,f32) += A(16x32,e4m3) * B(32x8,e4m3)
static __device__ __forceinline__ void mma16832(
    float* d, const uint32_t* a, const uint32_t* b) {
    asm volatile(
        "mma.sync.aligned.m16n8k32.row.col.f32.e4m3.e4m3.f32 "
        "{%0,%1,%2,%3}, {%4,%5,%6,%7}, {%8,%9}, {%0,%1,%2,%3};"
        : "+f"(d[0]), "+f"(d[1]), "+f"(d[2]), "+f"(d[3])
        : "r"(a[0]), "r"(a[1]), "r"(a[2]), "r"(a[3]), "r"(b[0]), "r"(b[1]));
}

static __device__ __forceinline__ uint32_t pack_fp8x4(
    float a, float b, float c, float d) {
    const __nv_fp8x2_storage_t lo =
        __nv_cvt_float2_to_fp8x2(make_float2(a, b), __NV_SATFINITE, __NV_E4M3);
    const __nv_fp8x2_storage_t hi =
        __nv_cvt_float2_to_fp8x2(make_float2(c, d), __NV_SATFINITE, __NV_E4M3);
    return (uint32_t)lo | ((uint32_t)hi << 16);
}

// ---------------------------------------------------------------------------
// Kernel 1: block-per-row normalize -> e4m3 (scale 16), fp32 diag, zeroing
//   128 threads/row; 2 float4 per tensor per thread (front-batched, MLP=4);
//   no serial tid-0 section (every thread folds the 4 warp partials).
// ---------------------------------------------------------------------------
__global__ void __launch_bounds__(128) norm_kernel(
    const float* __restrict__ x, const float* __restrict__ y) {
    const int i = blockIdx.x;
    const int tid = threadIdx.x;
    const int wid = tid >> 5, lane = tid & 31;

    const float4* xr = reinterpret_cast<const float4*>(x) + (size_t)i * 256;
    const float4* yr = reinterpret_cast<const float4*>(y) + (size_t)i * 256;
    const float4 x0 = xr[tid], x1 = xr[tid + 128];
    const float4 y0 = yr[tid], y1 = yr[tid + 128];

    float ssx = x0.x * x0.x + x0.y * x0.y + x0.z * x0.z + x0.w * x0.w
              + x1.x * x1.x + x1.y * x1.y + x1.z * x1.z + x1.w * x1.w;
    float ssy = y0.x * y0.x + y0.y * y0.y + y0.z * y0.z + y0.w * y0.w
              + y1.x * y1.x + y1.y * y1.y + y1.z * y1.z + y1.w * y1.w;
    float sxy = x0.x * y0.x + x0.y * y0.y + x0.z * y0.z + x0.w * y0.w
              + x1.x * y1.x + x1.y * y1.y + x1.z * y1.z + x1.w * y1.w;
#pragma unroll
    for (int m = 16; m; m >>= 1) {
        ssx += __shfl_xor_sync(0xffffffffu, ssx, m);
        ssy += __shfl_xor_sync(0xffffffffu, ssy, m);
        sxy += __shfl_xor_sync(0xffffffffu, sxy, m);
    }
    __shared__ float s0[4], s1[4], s2[4];
    if (lane == 0) { s0[wid] = ssx; s1[wid] = ssy; s2[wid] = sxy; }
    __syncthreads();
    const float a = s0[0] + s0[1] + s0[2] + s0[3];
    const float b = s1[0] + s1[1] + s1[2] + s1[3];
    const float c = s2[0] + s2[1] + s2[2] + s2[3];
    const float invx = 1.0f / fmaxf(sqrtf(a), EPSF);
    const float invy = 1.0f / fmaxf(sqrtf(b), EPSF);
    if (tid == 0) {
        g_diag[i] = c * invx * invy;
        g_rowsum[i] = 0.f;
        g_colsum[i] = 0.f;
    }
    const float qx = QSCALE * invx, qy = QSCALE * invy;
    uint32_t* ox = reinterpret_cast<uint32_t*>(g_xq + (size_t)i * DDIM);
    uint32_t* oy = reinterpret_cast<uint32_t*>(g_yq + (size_t)i * DDIM);
    ox[tid]       = pack_fp8x4(x0.x * qx, x0.y * qx, x0.z * qx, x0.w * qx);
    ox[tid + 128] = pack_fp8x4(x1.x * qx, x1.y * qx, x1.z * qx, x1.w * qx);
    oy[tid]       = pack_fp8x4(y0.x * qy, y0.y * qy, y0.z * qy, y0.w * qy);
    oy[tid + 128] = pack_fp8x4(y1.x * qy, y1.y * qy, y1.z * qy, y1.w * qy);
}

// ---------------------------------------------------------------------------
// Kernel 2: pipelined fp8 mma.sync GEMM tile + fused exp / row+col sums
//   grid = (32, 32) = 1024 CTAs; 512 threads; warp grid 4(m) x 4(n);
//   warp tile 32x32; 1 CTA/SM (full reg budget)
// ---------------------------------------------------------------------------
static __device__ __forceinline__ void load_stage(
    uint32_t sbase, int p, const uint8_t* gA, const uint8_t* gB, int tid) {
    const int s = p % STAGES;
    const uint32_t aBase = sbase + (uint32_t)(s * STAGE_BYTES);
    const uint32_t bBase = aBase + (uint32_t)(BM * RS);
    // A: 128 rows x 8 chunks(16B) = 1024 chunks, 2 per thread
#pragma unroll
    for (int r = 0; r < 2; ++r) {
        const int idx = tid + r * 512;
        const int row = idx >> 3, c = idx & 7;
        cp16(aBase + (uint32_t)(row * RS + c * 16),
             gA + (size_t)(p * BK) + (size_t)row * DDIM + c * 16);
    }
    // B: 128 rows x 8 chunks = 1024 chunks, 2 per thread
#pragma unroll
    for (int r = 0; r < 2; ++r) {
        const int idx = tid + r * 512;
        const int row = idx >> 3, c = idx & 7;
        cp16(bBase + (uint32_t)(row * RS + c * 16),
             gB + (size_t)(p * BK) + (size_t)row * DDIM + c * 16);
    }
    CP_COMMIT();
}

__global__ void __launch_bounds__(512, 1) gemm_exp_kernel() {
    extern __shared__ uint8_t smem[];
    const uint32_t sbase = smem_u32(smem);
    const int tid = threadIdx.x;
    const int lane = tid & 31;
    const int wid = tid >> 5;
    const int warp_m = wid & 3;        // 0..3 -> 32-row slice
    const int warp_n = wid >> 2;       // 0..3 -> 32-col slice
    const int i_base = blockIdx.x * BM;
    const int j_base = blockIdx.y * BN;
    const uint8_t* gA = g_xq + (size_t)i_base * DDIM;
    const uint8_t* gB = g_yq + (size_t)j_base * DDIM;

    float acc[2][4][4];
#pragma unroll
    for (int mi = 0; mi < 2; ++mi)
#pragma unroll
        for (int ni = 0; ni < 4; ++ni)
#pragma unroll
            for (int r = 0; r < 4; ++r) acc[mi][ni][r] = 0.f;

    load_stage(sbase, 0, gA, gB, tid);
    load_stage(sbase, 1, gA, gB, tid);
    load_stage(sbase, 2, gA, gB, tid);

    // ldmatrix: 16 rows x 32B; lanes 0-15 pick rows, lanes 16-31 add 16B
    const uint32_t lrow = (uint32_t)(lane & 15);
    const uint32_t koff = (uint32_t)((lane >> 4) * 16);

    for (int kt = 0; kt < KT; ++kt) {
        CP_WAIT(STAGES - 2);
        __syncthreads();              // single sync per stage (multistage-safe)
        if (kt + STAGES - 1 < KT)
            load_stage(sbase, kt + STAGES - 1, gA, gB, tid);

        const int s = kt % STAGES;
        const uint32_t aTile = sbase + (uint32_t)(s * STAGE_BYTES);
        const uint32_t bTile = aTile + (uint32_t)(BM * RS);
        const uint32_t aAddr0 = aTile + (warp_m * 32 + lrow) * RS + koff;
        const uint32_t bAddr0 = bTile + (warp_n * 32 + lrow) * RS + koff;

#pragma unroll
        for (int kk = 0; kk < 4; ++kk) {          // 4 x k32 = BK
            const uint32_t kb = (uint32_t)(kk * 32);
            uint32_t a[2][4];
#pragma unroll
            for (int mi = 0; mi < 2; ++mi)
                ldmatrix_x4(a[mi][0], a[mi][1], a[mi][2], a[mi][3],
                            aAddr0 + kb + (uint32_t)(mi * 16 * RS));
            uint32_t b[4][2];
#pragma unroll
            for (int p = 0; p < 2; ++p) {
                uint32_t r0, r1, r2, r3;
                ldmatrix_x4(r0, r1, r2, r3, bAddr0 + kb + (uint32_t)(p * 16 * RS));
                b[2 * p][0] = r0; b[2 * p + 1][0] = r1;
                b[2 * p][1] = r2; b[2 * p + 1][1] = r3;
            }
#pragma unroll
            for (int mi = 0; mi < 2; ++mi)
#pragma unroll
                for (int ni = 0; ni < 4; ++ni)
                    mma16832(acc[mi][ni], a[mi], b[ni]);
        }
    }
    __syncthreads();

    // ---------------- fused epilogue: exp + row/col sums ----------------
    float rs[2][2] = {{0.f, 0.f}, {0.f, 0.f}};   // [mi][row-half]
    float cs[4][2];
#pragma unroll
    for (int ni = 0; ni < 4; ++ni) { cs[ni][0] = 0.f; cs[ni][1] = 0.f; }

#pragma unroll
    for (int mi = 0; mi < 2; ++mi)
#pragma unroll
        for (int ni = 0; ni < 4; ++ni) {
            const float e0 = ex2f(acc[mi][ni][0] * K2LOG_S);
            const float e1 = ex2f(acc[mi][ni][1] * K2LOG_S);
            const float e2 = ex2f(acc[mi][ni][2] * K2LOG_S);
            const float e3 = ex2f(acc[mi][ni][3] * K2LOG_S);
            rs[mi][0] += e0 + e1;      // row = m0 + mi*16 + gid
            rs[mi][1] += e2 + e3;      // row + 8
            cs[ni][0] += e0 + e2;      // col = n0 + ni*8 + 2*tig
            cs[ni][1] += e1 + e3;      // col + 1
        }

    const int m0 = i_base + warp_m * 32;
    const int n0 = j_base + warp_n * 32;
    const int gid = lane >> 2, tig = lane & 3;

#pragma unroll
    for (int mi = 0; mi < 2; ++mi)
#pragma unroll
        for (int h = 0; h < 2; ++h) {
            float v = rs[mi][h];
            v += __shfl_xor_sync(0xffffffffu, v, 1);
            v += __shfl_xor_sync(0xffffffffu, v, 2);
            if (tig == 0)
                atomicAdd(&g_rowsum[m0 + mi * 16 + h * 8 + gid], v);
        }
#pragma unroll
    for (int ni = 0; ni < 4; ++ni)
#pragma unroll
        for (int h = 0; h < 2; ++h) {
            float v = cs[ni][h];
            v += __shfl_xor_sync(0xffffffffu, v, 4);
            v += __shfl_xor_sync(0xffffffffu, v, 8);
            v += __shfl_xor_sync(0xffffffffu, v, 16);
            if (gid == 0)
                atomicAdd(&g_colsum[n0 + ni * 8 + 2 * tig + h], v);
        }
}

// ---------------------------------------------------------------------------
// Kernel 3: final log-reduce -> scalar loss
// ---------------------------------------------------------------------------
__global__ void __launch_bounds__(256) finalize_kernel(float* __restrict__ out) {
    const int tid = threadIdx.x;
    const double extra = (double)BROWS * 1e-6 + 1e-6;
    double acc = 0.0;
    for (int i = tid; i < BROWS; i += 256) {
        const double t = 2.0 * (double)g_diag[i] / 0.07;
        acc += t - log((double)g_rowsum[i] + extra) - log((double)g_colsum[i] + extra);
    }
    __shared__ double sb[256];
    sb[tid] = acc;
    __syncthreads();
#pragma unroll
    for (int s = 128; s; s >>= 1) {
        if (tid < s) sb[tid] += sb[tid + s];
        __syncthreads();
    }
    if (tid == 0) out[0] = (float)(sb[0] * (-1.0 / (2.0 * (double)BROWS)));
}

// ---------------------------------------------------------------------------
extern "C" void kernel_launch(void* const* d_in, const int* in_sizes, int n_in,
                              void* d_out, int out_size) {
    const float* x = (const float*)d_in[0];
    const float* y = (const float*)d_in[1];
    float* out = (float*)d_out;

    static int configured = 0;
    if (!configured) {
        cudaFuncSetAttribute(gemm_exp_kernel,
                             cudaFuncAttributeMaxDynamicSharedMemorySize, SMEM_BYTES);
        configured = 1;
    }

    norm_kernel<<<BROWS, 128>>>(x, y);
    gemm_exp_kernel<<<dim3(BROWS / BM, BROWS / BN), 512, SMEM_BYTES>>>();
    finalize_kernel<<<1, 256>>>(out);
}